// round 15
// baseline (speedup 1.0000x reference)
#include <cuda_runtime.h>
#include <cuda_fp16.h>
#include <math.h>
#include <stdint.h>

// Problem constants
#define B_  2
#define C_  128
#define D_  4
#define H_  48
#define W_  48
#define NTOK (B_*D_*H_*W_)   // 18432
#define NHEAD 4
#define HD 32
#define KW 7

// Scratch (device globals — no allocation allowed)
__device__ float    g_t    [NTOK*128];
__device__ uint32_t g_qkvh [NTOK*192];   // fp16x2 qkv: Q[0:64) K[64:128) V[128:192) pairs
__device__ uint32_t g_ah   [NTOK*64];    // fp16x2 activations (ln out / attn out)
__device__ uint32_t g_bh   [NTOK*128];   // fp16x2 h1
// fp16x2 weights (packed k-pairs, PERMUTED within 8-pair groups)
__device__ uint32_t g_wh[65536];

#define PERMJ(j) ((j) < 4 ? 2*(j) : 2*(j)-7)

// ===========================================================================
// Helpers
// ===========================================================================
__device__ __forceinline__ void mma_fp16(float* c, const uint32_t* a, const uint32_t* b) {
    asm volatile(
        "mma.sync.aligned.m16n8k16.row.col.f32.f16.f16.f32 "
        "{%0,%1,%2,%3}, {%4,%5,%6,%7}, {%8,%9}, {%0,%1,%2,%3};"
        : "+f"(c[0]), "+f"(c[1]), "+f"(c[2]), "+f"(c[3])
        : "r"(a[0]), "r"(a[1]), "r"(a[2]), "r"(a[3]), "r"(b[0]), "r"(b[1]));
}

__device__ __forceinline__ uint32_t f22h2(float x0, float x1) {
    __half2 h = __floats2half2_rn(x0, x1);
    return *reinterpret_cast<uint32_t*>(&h);
}

#define CP_ASYNC16(dst_u32, src_ptr) \
    asm volatile("cp.async.cg.shared.global [%0], [%1], 16;" \
        :: "r"(dst_u32), "l"(__cvta_generic_to_global(src_ptr)) : "memory")
#define CP_COMMIT() asm volatile("cp.async.commit_group;" ::: "memory")
#define CP_WAIT1()  asm volatile("cp.async.wait_group 1;" ::: "memory")
#define CP_WAIT0()  asm volatile("cp.async.wait_group 0;" ::: "memory")

// ===========================================================================
// Weight convert + permute (fp16 pairs)
// ===========================================================================
__global__ void wsplit_kernel(const float* __restrict__ qkv_w,
                              const float* __restrict__ proj_w,
                              const float* __restrict__ fc1_w,
                              const float* __restrict__ fc2_w) {
    int i = blockIdx.x * 256 + threadIdx.x;
    const float* src;
    int li;
    if (i < 24576)      { src = qkv_w;  li = i; }
    else if (i < 32768) { src = proj_w; li = i - 24576; }
    else if (i < 49152) { src = fc1_w;  li = i - 32768; }
    else                { src = fc2_w;  li = i - 49152; }
    float2 v = *reinterpret_cast<const float2*>(src + 2 * li);
    int dst = (i & ~7) | PERMJ(i & 7);
    g_wh[dst] = f22h2(v.x, v.y);
}

// ===========================================================================
// Fused LN + fp16 convert + permute: warp per token -> ah
// ===========================================================================
__global__ void ln_prep_kernel(const float* __restrict__ in,
                               const float* __restrict__ w,
                               const float* __restrict__ b,
                               uint32_t* __restrict__ ah) {
    int n = blockIdx.x * 8 + (threadIdx.x >> 5);
    int lane = threadIdx.x & 31;
    float4 v = *reinterpret_cast<const float4*>(in + (long)n*128 + lane*4);
    float s  = v.x + v.y + v.z + v.w;
    float s2 = v.x*v.x + v.y*v.y + v.z*v.z + v.w*v.w;
    #pragma unroll
    for (int o = 16; o > 0; o >>= 1) {
        s  += __shfl_xor_sync(0xffffffffu, s,  o);
        s2 += __shfl_xor_sync(0xffffffffu, s2, o);
    }
    float m    = s  * (1.0f/128.0f);
    float rstd = rsqrtf(s2 * (1.0f/128.0f) - m*m + 1e-5f);
    float4 wv = *reinterpret_cast<const float4*>(w + lane*4);
    float4 bv = *reinterpret_cast<const float4*>(b + lane*4);
    float y0 = (v.x - m) * rstd * wv.x + bv.x;
    float y1 = (v.y - m) * rstd * wv.y + bv.y;
    float y2 = (v.z - m) * rstd * wv.z + bv.z;
    float y3 = (v.w - m) * rstd * wv.w + bv.w;
    int p0 = 2*lane, p1 = 2*lane + 1;
    int i0 = (p0 & ~7) | PERMJ(p0 & 7);
    int i1 = (p1 & ~7) | PERMJ(p1 & 7);
    long base = (long)n * 64;
    ah[base + i0] = f22h2(y0, y1);
    ah[base + i1] = f22h2(y2, y3);
}

// ===========================================================================
// Persistent-A fp16 GEMM: 1 CTA per 128-token slab (grid = 144).
// A panel (128 x K) staged ONCE in smem; loop over MBLK 64-col blocks
// with double-buffered cp.async B tiles.
// EPI: 2 bias+residual; 3 bias+residual+transposed store;
//      4 bias+GELU+fp16; 5 qkv fp16 epilogue
// ===========================================================================
template<int EPI, int K, int MBLK>
__global__ void __launch_bounds__(256, 2)
gemm_ps_kernel(const uint32_t* __restrict__ AHg,
               const uint32_t* __restrict__ WH,
               const float* __restrict__ bias,
               float* __restrict__ out,
               uint32_t* __restrict__ outH,
               const float* __restrict__ resid,
               int M) {
    constexpr int Kp  = K / 2;        // u32 per row
    constexpr int AST = Kp + 8;       // padded stride ((Kp+8) mod 32 == 8 -> conflict-free)
    constexpr int ASZ = 128 * AST;
    constexpr int BSZ = 64 * AST;
    constexpr int SPR = Kp / 4;       // 16B segs per row

    extern __shared__ uint32_t smg[];
    uint32_t smb = (uint32_t)__cvta_generic_to_shared(smg);

    int tid = threadIdx.x;
    int wid = tid >> 5, lane = tid & 31;
    int warp_m = wid & 3;
    int warp_n = wid >> 2;
    int gid = lane >> 2;
    int tig = lane & 3;

    int n0 = blockIdx.x * 128;

    // ---- stage A panel (bundled into B0's commit group)
    #pragma unroll
    for (int r = 0; r < (128 * SPR) / 256; r++) {
        int seg = r * 256 + tid;
        int row = seg / SPR, q = seg % SPR;
        CP_ASYNC16(smb + (row * AST + q * 4) * 4, AHg + (long)(n0 + row) * Kp + q * 4);
    }
    auto issueB = [&](int mb, int s) {
        uint32_t base = smb + (uint32_t)(ASZ + s * BSZ) * 4u;
        int m0 = mb * 64;
        #pragma unroll
        for (int r = 0; r < (64 * SPR) / 256; r++) {
            int seg = r * 256 + tid;
            int row = seg / SPR, q = seg % SPR;
            CP_ASYNC16(base + (row * AST + q * 4) * 4, WH + (long)(m0 + row) * Kp + q * 4);
        }
        CP_COMMIT();
    };
    issueB(0, 0);     // group0 = A + B0
    issueB(1, 1);     // group1 = B1

    for (int mb = 0; mb < MBLK; mb++) {
        if (mb + 1 < MBLK) { CP_WAIT1(); } else { CP_WAIT0(); }
        __syncthreads();

        uint32_t* As = smg;
        uint32_t* Bs = smg + ASZ + (mb & 1) * BSZ;

        float acc[2][4][4];
        #pragma unroll
        for (int mt = 0; mt < 2; mt++)
            #pragma unroll
            for (int nt = 0; nt < 4; nt++)
                #pragma unroll
                for (int i = 0; i < 4; i++) acc[mt][nt][i] = 0.f;

        #pragma unroll
        for (int ks = 0; ks < K / 16; ks++) {
            int jc = ks * 8 + 2 * tig;
            uint32_t ahi[2][4];
            #pragma unroll
            for (int mt = 0; mt < 2; mt++) {
                int r = warp_m * 32 + mt * 16 + gid;
                uint2 h0 = *reinterpret_cast<uint2*>(&As[r * AST + jc]);
                uint2 h1 = *reinterpret_cast<uint2*>(&As[(r + 8) * AST + jc]);
                ahi[mt][0] = h0.x; ahi[mt][1] = h1.x; ahi[mt][2] = h0.y; ahi[mt][3] = h1.y;
            }
            uint32_t bhi[4][2];
            #pragma unroll
            for (int nt = 0; nt < 4; nt++) {
                int br = warp_n * 32 + nt * 8 + gid;
                uint2 bh = *reinterpret_cast<uint2*>(&Bs[br * AST + jc]);
                bhi[nt][0] = bh.x; bhi[nt][1] = bh.y;
            }
            #pragma unroll
            for (int mt = 0; mt < 2; mt++)
                #pragma unroll
                for (int nt = 0; nt < 4; nt++)
                    mma_fp16(acc[mt][nt], ahi[mt], bhi[nt]);
        }
        __syncthreads();   // all warps done with B buf (mb&1)

        if (mb + 2 < MBLK) issueB(mb + 2, mb & 1);

        // ---- epilogue for this m-block (overlaps next B load)
        int row_base = n0 + warp_m * 32;
        int col_base = mb * 64 + warp_n * 32;
        #pragma unroll
        for (int nt = 0; nt < 4; nt++) {
            int col = col_base + nt * 8 + 2 * tig;
            float b0 = bias[col], b1 = bias[col + 1];
            #pragma unroll
            for (int mt = 0; mt < 2; mt++) {
                #pragma unroll
                for (int half = 0; half < 2; half++) {
                    int r = row_base + mt * 16 + gid + half * 8;
                    float v0 = acc[mt][nt][half * 2 + 0] + b0;
                    float v1 = acc[mt][nt][half * 2 + 1] + b1;
                    if (EPI == 5) {
                        int idx;
                        if (col < 128) {
                            const float sc = 0.17677669529663687f;
                            v0 *= sc; v1 *= sc;
                            int p = col >> 1;
                            idx = (p & ~7) | PERMJ(p & 7);
                        } else if (col < 256) {
                            int p = (col - 128) >> 1;
                            idx = 64 + ((p & ~7) | PERMJ(p & 7));
                        } else {
                            idx = 128 + ((col - 256) >> 1);
                        }
                        outH[(long)r * 192 + idx] = f22h2(v0, v1);
                    } else if (EPI == 4) {
                        v0 = 0.5f * v0 * (1.0f + erff(v0 * 0.70710678118654752f));
                        v1 = 0.5f * v1 * (1.0f + erff(v1 * 0.70710678118654752f));
                        int p = col >> 1;
                        int idx = (p & ~7) | PERMJ(p & 7);
                        outH[(long)r * 128 + idx] = f22h2(v0, v1);
                    } else if (EPI == 3) {
                        float2 rv = *reinterpret_cast<const float2*>(resid + (long)r * 128 + col);
                        v0 += rv.x; v1 += rv.y;
                        long o = (long)r + (r >= 9216 ? 1170432L : 0L) + (long)col * 9216;
                        out[o]        = v0;
                        out[o + 9216] = v1;
                    } else {
                        float2* dst = reinterpret_cast<float2*>(out + (long)r * M + col);
                        if (EPI == 2) {
                            float2 old = *dst;
                            v0 += old.x; v1 += old.y;
                        }
                        float2 st; st.x = v0; st.y = v1;
                        *dst = st;
                    }
                }
            }
        }
    }
}

// ===========================================================================
// fp16 tensor-core neighborhood attention (unchanged from R13/R14)
// ===========================================================================
#define AGSTR 24
#define VSTP  116
#define PSTP  68
#define ATTN_SMEM_U32 (224*AGSTR + 32*VSTP + 170)   // 9258

__global__ void __launch_bounds__(128, 4)
attn_mma_kernel(const uint32_t* __restrict__ inH,
                const float* __restrict__ rpb,
                uint32_t* __restrict__ outH) {
    extern __shared__ uint32_t smu[];
    uint32_t* Ks = smu;
    uint32_t* Vt = Ks + 224*AGSTR;
    float*    rb = reinterpret_cast<float*>(Vt + 32*VSTP);

    int tile = blockIdx.x, head = blockIdx.y, bd = blockIdx.z;
    int h0 = (tile / 6) * 8;
    int w0 = (tile % 6) * 8;
    int kh0 = min(max(h0 - 3, 0), H_ - KW);
    int kw0 = min(max(w0 - 3, 0), W_ - KW);
    int tid = threadIdx.x;

    for (int e = tid; e < 196*4; e += 128) {
        int key = e >> 2, q = e & 3;
        int kr = key / 14, kc = key % 14;
        int gh = min(kh0 + kr, H_-1);
        int gw = min(kw0 + kc, W_-1);
        long tok = ((long)(bd*H_ + gh))*W_ + gw;
        long src = tok*192 + 64 + head*16 + q*4;
        *reinterpret_cast<uint4*>(&Ks[key*AGSTR + q*4]) = *reinterpret_cast<const uint4*>(inH + src);
    }
    for (int e = tid; e < 28*6; e += 128) {
        int key = 196 + e / 6, q = e % 6;
        *reinterpret_cast<uint4*>(&Ks[key*AGSTR + q*4]) = make_uint4(0,0,0,0);
    }
    for (int e = tid; e < 98*4; e += 128) {
        int kp = e >> 2, pq = e & 3;
        int keyA = 2*kp;
        int kr = keyA / 14, kc = keyA % 14;
        int gh = min(kh0 + kr, H_-1);
        int gwA = min(kw0 + kc, W_-1);
        int gwB = min(kw0 + kc + 1, W_-1);
        long rowb = ((long)(bd*H_ + gh))*W_;
        long sA = (rowb + gwA)*192 + 128 + head*16 + pq*4;
        long sB = (rowb + gwB)*192 + 128 + head*16 + pq*4;
        uint4 HA = *reinterpret_cast<const uint4*>(inH + sA);
        uint4 HB = *reinterpret_cast<const uint4*>(inH + sB);
        uint32_t ha[4] = {HA.x, HA.y, HA.z, HA.w};
        uint32_t hb[4] = {HB.x, HB.y, HB.z, HB.w};
        #pragma unroll
        for (int j = 0; j < 4; j++) {
            int pp = pq*4 + j;
            Vt[(2*pp+0)*VSTP + kp] = __byte_perm(ha[j], hb[j], 0x5410);
            Vt[(2*pp+1)*VSTP + kp] = __byte_perm(ha[j], hb[j], 0x7632);
        }
    }
    for (int e = tid; e < 32*14; e += 128) {
        int dm = e / 14, kp = 98 + (e % 14);
        Vt[dm*VSTP + kp] = 0;
    }
    for (int i = tid; i < 169; i += 128) rb[i] = rpb[head*169 + i];
    __syncthreads();

    int warp = tid >> 5, lane = tid & 31;
    int gid = lane >> 2, tig = lane & 3;

    int hq0 = h0 + 2*warp;
    int hq1 = hq0 + 1;
    int wq  = w0 + gid;
    long tok0 = (long)(bd*H_ + hq0)*W_ + wq;
    long tok1 = tok0 + W_;
    int rel0 = min(max(hq0-3, 0), H_-KW) - kh0;
    int rel1 = min(max(hq1-3, 0), H_-KW) - kh0;
    int ws   = min(max(wq-3, 0), W_-KW) - kw0;
    int n_base = ((min(rel0, rel1) * 14) >> 3) * 8;

    uint32_t qh[2][4];
    #pragma unroll
    for (int ks = 0; ks < 2; ks++) {
        long o0 = tok0*192 + head*16 + ks*8 + 2*tig;
        long o1 = tok1*192 + head*16 + ks*8 + 2*tig;
        uint2 h0v = *reinterpret_cast<const uint2*>(inH + o0);
        uint2 h1v = *reinterpret_cast<const uint2*>(inH + o1);
        qh[ks][0] = h0v.x; qh[ks][1] = h1v.x; qh[ks][2] = h0v.y; qh[ks][3] = h1v.y;
    }

    float acc[15][4];
    #pragma unroll
    for (int nt = 0; nt < 15; nt++)
        #pragma unroll
        for (int i = 0; i < 4; i++) acc[nt][i] = 0.f;

    #pragma unroll
    for (int nt = 0; nt < 15; nt++) {
        int key = n_base + nt*8 + gid;
        #pragma unroll
        for (int ks = 0; ks < 2; ks++) {
            int o = key*AGSTR + ks*8 + 2*tig;
            uint2 bhv = *reinterpret_cast<uint2*>(&Ks[o]);
            uint32_t bh[2] = { bhv.x, bhv.y };
            mma_fp16(acc[nt], qh[ks], bh);
        }
    }

    int bh0c = kh0 - hq0 + 6;
    int bh1c = kh0 - hq1 + 6;
    int bwc  = kw0 - wq + 6;
    float mx0 = -1e30f, mx1 = -1e30f;
    #pragma unroll
    for (int nt = 0; nt < 15; nt++) {
        #pragma unroll
        for (int cc = 0; cc < 2; cc++) {
            int n = n_base + nt*8 + 2*tig + cc;
            int kr = n / 14;
            int kc = n - kr*14;
            bool vw = (unsigned)(kc - ws) <= 6u;
            bool v0 = vw && (unsigned)(kr - rel0) <= 6u;
            bool v1 = vw && (unsigned)(kr - rel1) <= 6u;
            float s0 = v0 ? acc[nt][cc]   + rb[(bh0c+kr)*13 + bwc + kc] : -1e30f;
            float s1 = v1 ? acc[nt][2+cc] + rb[(bh1c+kr)*13 + bwc + kc] : -1e30f;
            acc[nt][cc]   = s0;
            acc[nt][2+cc] = s1;
            mx0 = fmaxf(mx0, s0);
            mx1 = fmaxf(mx1, s1);
        }
    }
    mx0 = fmaxf(mx0, __shfl_xor_sync(0xffffffffu, mx0, 1));
    mx0 = fmaxf(mx0, __shfl_xor_sync(0xffffffffu, mx0, 2));
    mx1 = fmaxf(mx1, __shfl_xor_sync(0xffffffffu, mx1, 1));
    mx1 = fmaxf(mx1, __shfl_xor_sync(0xffffffffu, mx1, 2));

    float sum0 = 0.f, sum1 = 0.f;
    #pragma unroll
    for (int nt = 0; nt < 15; nt++) {
        #pragma unroll
        for (int cc = 0; cc < 2; cc++) {
            float e0 = __expf(acc[nt][cc]   - mx0);
            float e1 = __expf(acc[nt][2+cc] - mx1);
            acc[nt][cc]   = e0;
            acc[nt][2+cc] = e1;
            sum0 += e0;
            sum1 += e1;
        }
    }
    sum0 += __shfl_xor_sync(0xffffffffu, sum0, 1);
    sum0 += __shfl_xor_sync(0xffffffffu, sum0, 2);
    sum1 += __shfl_xor_sync(0xffffffffu, sum1, 1);
    sum1 += __shfl_xor_sync(0xffffffffu, sum1, 2);
    float inv0 = 1.0f / sum0;
    float inv1 = 1.0f / sum1;

    __syncthreads();
    uint32_t* Pw = smu + warp * (16 * PSTP);
    #pragma unroll
    for (int nt = 0; nt < 15; nt++) {
        Pw[gid*PSTP + nt*4 + tig]     = f22h2(acc[nt][0], acc[nt][1]);
        Pw[(gid+8)*PSTP + nt*4 + tig] = f22h2(acc[nt][2], acc[nt][3]);
    }
    Pw[gid*PSTP + 60 + tig] = 0;
    Pw[(gid+8)*PSTP + 60 + tig] = 0;
    __syncwarp();

    int nb2 = n_base >> 1;
    float o[4][4];
    #pragma unroll
    for (int nt = 0; nt < 4; nt++)
        #pragma unroll
        for (int i = 0; i < 4; i++) o[nt][i] = 0.f;

    #pragma unroll
    for (int kt = 0; kt < 8; kt++) {
        int p0 = gid*PSTP + kt*8 + tig;
        int p1 = (gid+8)*PSTP + kt*8 + tig;
        uint32_t ph[4] = { Pw[p0], Pw[p1], Pw[p0 + 4], Pw[p1 + 4] };
        #pragma unroll
        for (int nt = 0; nt < 4; nt++) {
            int vr = (nt*8 + gid)*VSTP + nb2 + kt*8 + tig;
            uint32_t vh[2] = { Vt[vr], Vt[vr + 4] };
            mma_fp16(o[nt], ph, vh);
        }
    }

    #pragma unroll
    for (int nt = 0; nt < 4; nt++) {
        int d = head*32 + nt*8 + 2*tig;
        int p = d >> 1;
        int idx = (p & ~7) | PERMJ(p & 7);
        outH[tok0*64 + idx] = f22h2(o[nt][0]*inv0, o[nt][1]*inv0);
        outH[tok1*64 + idx] = f22h2(o[nt][2]*inv1, o[nt][3]*inv1);
    }
}

// ---------------------------------------------------------------------------
// Transpose in: x (B,C,D,H,W) -> t (N=B*D*H*W, C)
// ---------------------------------------------------------------------------
__global__ void t_in_kernel(const float* __restrict__ x, float* __restrict__ t) {
    __shared__ float sm[16][17];
    int bz = blockIdx.z;
    int b = bz / (D_*H_);
    int rem = bz % (D_*H_);
    int d = rem / H_;
    int h = rem % H_;
    int w = blockIdx.x*16 + threadIdx.x;
    int c = blockIdx.y*16 + threadIdx.y;
    sm[threadIdx.y][threadIdx.x] =
        x[(( (long)b*C_ + c)*D_ + d)*(H_*W_) + h*W_ + w];
    __syncthreads();
    int c2 = blockIdx.y*16 + threadIdx.x;
    int w2 = blockIdx.x*16 + threadIdx.y;
    t[((((b*D_ + d)*H_ + h)*W_ + w2) * (long)C_) + c2] = sm[threadIdx.x][threadIdx.y];
}

// ---------------------------------------------------------------------------
// Launch
// ---------------------------------------------------------------------------
extern "C" void kernel_launch(void* const* d_in, const int* in_sizes, int n_in,
                              void* d_out, int out_size) {
    const float* x      = (const float*)d_in[0];
    const float* n1w    = (const float*)d_in[1];
    const float* n1b    = (const float*)d_in[2];
    const float* qkv_w  = (const float*)d_in[3];
    const float* qkv_b  = (const float*)d_in[4];
    const float* rpb    = (const float*)d_in[5];
    const float* proj_w = (const float*)d_in[6];
    const float* proj_b = (const float*)d_in[7];
    const float* n2w    = (const float*)d_in[8];
    const float* n2b    = (const float*)d_in[9];
    const float* fc1_w  = (const float*)d_in[10];
    const float* fc1_b  = (const float*)d_in[11];
    const float* fc2_w  = (const float*)d_in[12];
    const float* fc2_b  = (const float*)d_in[13];
    float* out = (float*)d_out;

    float *t_p;
    uint32_t *wh_p, *ah_p, *bh_p, *qh_p;
    cudaGetSymbolAddress((void**)&t_p,  g_t);
    cudaGetSymbolAddress((void**)&wh_p, g_wh);
    cudaGetSymbolAddress((void**)&ah_p, g_ah);
    cudaGetSymbolAddress((void**)&bh_p, g_bh);
    cudaGetSymbolAddress((void**)&qh_p, g_qkvh);

    // smem sizes: K=128 -> (128+2*64)*72*4 = 73728 ; K=256 -> (128+2*64)*136*4 = 139264
    int smem128 = (128 + 2*64) * (64 + 8) * 4;
    int smem256 = (128 + 2*64) * (128 + 8) * 4;
    int attn_smem = ATTN_SMEM_U32 * (int)sizeof(uint32_t);
    cudaFuncSetAttribute(attn_mma_kernel, cudaFuncAttributeMaxDynamicSharedMemorySize, attn_smem);
    cudaFuncSetAttribute(gemm_ps_kernel<5,128,6>, cudaFuncAttributeMaxDynamicSharedMemorySize, smem128);
    cudaFuncSetAttribute(gemm_ps_kernel<2,128,2>, cudaFuncAttributeMaxDynamicSharedMemorySize, smem128);
    cudaFuncSetAttribute(gemm_ps_kernel<4,128,4>, cudaFuncAttributeMaxDynamicSharedMemorySize, smem128);
    cudaFuncSetAttribute(gemm_ps_kernel<3,256,2>, cudaFuncAttributeMaxDynamicSharedMemorySize, smem256);

    dim3 tb(16, 16);
    dim3 tg(W_/16, C_/16, B_*D_*H_);

    // 0. convert weights to fp16 pairs
    wsplit_kernel<<<256, 256>>>(qkv_w, proj_w, fc1_w, fc2_w);
    // 1. transpose in
    t_in_kernel<<<tg, tb>>>(x, t_p);
    // 2. LN1 + fp16 convert
    ln_prep_kernel<<<NTOK/8, 256>>>(t_p, n1w, n1b, ah_p);
    // 3. qkv GEMM -> fp16 Q(scaled)/K/V   (M=384, K=128, 6 m-blocks)
    gemm_ps_kernel<5,128,6><<<NTOK/128, 256, smem128>>>(
        ah_p, wh_p, qkv_b, nullptr, qh_p, nullptr, 384);
    // 4. neighborhood attention -> fp16 out
    attn_mma_kernel<<<dim3(36, NHEAD, B_*D_), 128, attn_smem>>>(qh_p, rpb, ah_p);
    // 5. t += attn @ proj_w^T + b     (M=128, K=128, 2 m-blocks)
    gemm_ps_kernel<2,128,2><<<NTOK/128, 256, smem128>>>(
        ah_p, wh_p + 24576, proj_b, t_p, nullptr, nullptr, 128);
    // 6. LN2 + fp16 convert
    ln_prep_kernel<<<NTOK/8, 256>>>(t_p, n2w, n2b, ah_p);
    // 7. h1 = gelu(LN2(t) @ fc1_w^T + b) -> fp16  (M=256, K=128, 4 m-blocks)
    gemm_ps_kernel<4,128,4><<<NTOK/128, 256, smem128>>>(
        ah_p, wh_p + 32768, fc1_b, nullptr, bh_p, nullptr, 256);
    // 8. out = transpose(t + h1 @ fc2_w^T + b)   (M=128, K=256, 2 m-blocks)
    gemm_ps_kernel<3,256,2><<<NTOK/128, 256, smem256>>>(
        bh_p, wh_p + 49152, fc2_b, out, nullptr, t_p, 128);
}

// round 17
// speedup vs baseline: 1.0860x; 1.0860x over previous
#include <cuda_runtime.h>
#include <cuda_fp16.h>
#include <math.h>
#include <stdint.h>

// Problem constants
#define B_  2
#define C_  128
#define D_  4
#define H_  48
#define W_  48
#define NTOK (B_*D_*H_*W_)   // 18432
#define NHEAD 4
#define HD 32
#define KW 7

// Scratch (device globals — no allocation allowed)
__device__ float    g_t    [NTOK*128];
__device__ uint32_t g_qkvh [NTOK*192];   // fp16x2 qkv: Q[0:64) K[64:128) V[128:192) pairs
__device__ uint32_t g_ah   [NTOK*64];    // fp16x2 activations (ln out / attn out)
__device__ uint32_t g_bh   [NTOK*128];   // fp16x2 h1
// fp16x2 weights (packed k-pairs, PERMUTED within 8-pair groups)
__device__ uint32_t g_wh[65536];

#define PERMJ(j) ((j) < 4 ? 2*(j) : 2*(j)-7)

// ===========================================================================
// Helpers
// ===========================================================================
__device__ __forceinline__ void mma_fp16(float* c, const uint32_t* a, const uint32_t* b) {
    asm volatile(
        "mma.sync.aligned.m16n8k16.row.col.f32.f16.f16.f32 "
        "{%0,%1,%2,%3}, {%4,%5,%6,%7}, {%8,%9}, {%0,%1,%2,%3};"
        : "+f"(c[0]), "+f"(c[1]), "+f"(c[2]), "+f"(c[3])
        : "r"(a[0]), "r"(a[1]), "r"(a[2]), "r"(a[3]), "r"(b[0]), "r"(b[1]));
}

__device__ __forceinline__ uint32_t f22h2(float x0, float x1) {
    __half2 h = __floats2half2_rn(x0, x1);
    return *reinterpret_cast<uint32_t*>(&h);
}

#define CP_ASYNC16(dst_u32, src_ptr) \
    asm volatile("cp.async.cg.shared.global [%0], [%1], 16;" \
        :: "r"(dst_u32), "l"(__cvta_generic_to_global(src_ptr)) : "memory")
#define CP_COMMIT() asm volatile("cp.async.commit_group;" ::: "memory")
#define CP_WAIT1()  asm volatile("cp.async.wait_group 1;" ::: "memory")
#define CP_WAIT0()  asm volatile("cp.async.wait_group 0;" ::: "memory")

// ===========================================================================
// Weight convert + permute (fp16 pairs)
// ===========================================================================
__global__ void wsplit_kernel(const float* __restrict__ qkv_w,
                              const float* __restrict__ proj_w,
                              const float* __restrict__ fc1_w,
                              const float* __restrict__ fc2_w) {
    int i = blockIdx.x * 256 + threadIdx.x;
    const float* src;
    int li;
    if (i < 24576)      { src = qkv_w;  li = i; }
    else if (i < 32768) { src = proj_w; li = i - 24576; }
    else if (i < 49152) { src = fc1_w;  li = i - 32768; }
    else                { src = fc2_w;  li = i - 49152; }
    float2 v = *reinterpret_cast<const float2*>(src + 2 * li);
    int dst = (i & ~7) | PERMJ(i & 7);
    g_wh[dst] = f22h2(v.x, v.y);
}

// ===========================================================================
// Fused transpose-in + LN1 + fp16 convert: one block per (b,d,h) row.
// Reads x (B,C,D,H,W), writes g_t (token-major fp32) and ah (fp16 pairs).
// Stride 132 floats = 528 B (16B aligned; 132 mod 32 = 4, LN loads conflict-free).
// ===========================================================================
#define TLN_STR 132

__global__ void __launch_bounds__(256, 4)
t_ln_kernel(const float* __restrict__ x,
            const float* __restrict__ w,
            const float* __restrict__ b,
            float* __restrict__ t,
            uint32_t* __restrict__ ah) {
    __shared__ float sm[48 * TLN_STR];
    int bz = blockIdx.x;                 // b*D*H + d*H + h
    int bb = bz / (D_*H_);
    int rem = bz % (D_*H_);
    int d = rem / H_;
    int h = rem % H_;
    int tid = threadIdx.x;

    const float* xb = x + ((long)bb * C_ * D_ + (long)d) * (H_*W_) + h * W_;
    // load 128 c x 48 w (transpose through smem)
    #pragma unroll
    for (int k = 0; k < 24; k++) {
        int idx = k * 256 + tid;         // 0..6143
        int c = idx / 48, wv = idx - c * 48;
        sm[wv * TLN_STR + c] = xb[(long)c * (D_*H_*W_) + wv];
    }
    __syncthreads();

    int warp = tid >> 5, lane = tid & 31;
    long nbase = (long)bz * 48;
    #pragma unroll
    for (int i = 0; i < 6; i++) {
        int tok = warp * 6 + i;
        float4 v = *reinterpret_cast<const float4*>(&sm[tok * TLN_STR + lane * 4]);
        float s  = v.x + v.y + v.z + v.w;
        float s2 = v.x*v.x + v.y*v.y + v.z*v.z + v.w*v.w;
        #pragma unroll
        for (int o = 16; o > 0; o >>= 1) {
            s  += __shfl_xor_sync(0xffffffffu, s,  o);
            s2 += __shfl_xor_sync(0xffffffffu, s2, o);
        }
        float m    = s  * (1.0f/128.0f);
        float rstd = rsqrtf(s2 * (1.0f/128.0f) - m*m + 1e-5f);
        float4 wv4 = *reinterpret_cast<const float4*>(w + lane*4);
        float4 bv4 = *reinterpret_cast<const float4*>(b + lane*4);
        float y0 = (v.x - m) * rstd * wv4.x + bv4.x;
        float y1 = (v.y - m) * rstd * wv4.y + bv4.y;
        float y2 = (v.z - m) * rstd * wv4.z + bv4.z;
        float y3 = (v.w - m) * rstd * wv4.w + bv4.w;
        long n = nbase + tok;
        *reinterpret_cast<float4*>(t + n*128 + lane*4) = v;
        int p0 = 2*lane, p1 = 2*lane + 1;
        int i0 = (p0 & ~7) | PERMJ(p0 & 7);
        int i1 = (p1 & ~7) | PERMJ(p1 & 7);
        ah[n*64 + i0] = f22h2(y0, y1);
        ah[n*64 + i1] = f22h2(y2, y3);
    }
}

// ===========================================================================
// LN + fp16 convert (for LN2): warp per token -> ah
// ===========================================================================
__global__ void ln_prep_kernel(const float* __restrict__ in,
                               const float* __restrict__ w,
                               const float* __restrict__ b,
                               uint32_t* __restrict__ ah) {
    int n = blockIdx.x * 8 + (threadIdx.x >> 5);
    int lane = threadIdx.x & 31;
    float4 v = *reinterpret_cast<const float4*>(in + (long)n*128 + lane*4);
    float s  = v.x + v.y + v.z + v.w;
    float s2 = v.x*v.x + v.y*v.y + v.z*v.z + v.w*v.w;
    #pragma unroll
    for (int o = 16; o > 0; o >>= 1) {
        s  += __shfl_xor_sync(0xffffffffu, s,  o);
        s2 += __shfl_xor_sync(0xffffffffu, s2, o);
    }
    float m    = s  * (1.0f/128.0f);
    float rstd = rsqrtf(s2 * (1.0f/128.0f) - m*m + 1e-5f);
    float4 wv = *reinterpret_cast<const float4*>(w + lane*4);
    float4 bv = *reinterpret_cast<const float4*>(b + lane*4);
    float y0 = (v.x - m) * rstd * wv.x + bv.x;
    float y1 = (v.y - m) * rstd * wv.y + bv.y;
    float y2 = (v.z - m) * rstd * wv.z + bv.z;
    float y3 = (v.w - m) * rstd * wv.w + bv.w;
    int p0 = 2*lane, p1 = 2*lane + 1;
    int i0 = (p0 & ~7) | PERMJ(p0 & 7);
    int i1 = (p1 & ~7) | PERMJ(p1 & 7);
    long base = (long)n * 64;
    ah[base + i0] = f22h2(y0, y1);
    ah[base + i1] = f22h2(y2, y3);
}

// ===========================================================================
// fp16 tensor-core GEMM: cp.async 2-stage ring, 64-wide k-chunks (R14 config)
// EPI: 2 bias+residual; 3 bias+residual+transposed store;
//      4 bias+GELU+fp16; 5 qkv fp16 epilogue
// ===========================================================================
#define GSTR 40
#define STAGE_U32 7680
#define GEMM_SMEM (2 * STAGE_U32 * 4)   // 61440 B -> 3 CTAs/SM

template<int EPI>
__global__ void __launch_bounds__(256, 3)
gemm_cp_kernel(const uint32_t* __restrict__ AHg,
               const uint32_t* __restrict__ WH,
               const float* __restrict__ bias,
               float* __restrict__ out,
               uint32_t* __restrict__ outH,
               const float* __restrict__ resid,
               int M, int K) {
    extern __shared__ uint32_t smg[];
    uint32_t smb = (uint32_t)__cvta_generic_to_shared(smg);

    int tid = threadIdx.x;
    int wid = tid >> 5, lane = tid & 31;
    int warp_m = wid & 3;
    int warp_n = wid >> 2;
    int gid = lane >> 2;
    int tig = lane & 3;

    int n0 = blockIdx.y * 128;
    int m0 = blockIdx.x * 64;
    int Kp = K >> 1;
    int nch = K >> 6;

    float acc[2][4][4];
    #pragma unroll
    for (int mt = 0; mt < 2; mt++)
        #pragma unroll
        for (int nt = 0; nt < 4; nt++)
            #pragma unroll
            for (int i = 0; i < 4; i++) acc[mt][nt][i] = 0.f;

    auto issue = [&](int ch, int s) {
        uint32_t base = smb + (uint32_t)(s * STAGE_U32) * 4u;
        long ka = (long)ch * 32;
        #pragma unroll
        for (int r = 0; r < 4; r++) {
            int seg = r * 256 + tid;
            int row = seg >> 3, q = seg & 7;
            CP_ASYNC16(base + (row*GSTR + q*4)*4, AHg + (long)(n0 + row)*Kp + ka + q*4);
        }
        #pragma unroll
        for (int r = 0; r < 2; r++) {
            int seg = r * 256 + tid;
            int row = seg >> 3, q = seg & 7;
            CP_ASYNC16(base + (5120 + row*GSTR + q*4)*4, WH + (long)(m0 + row)*Kp + ka + q*4);
        }
        CP_COMMIT();
    };

    issue(0, 0);
    if (nch > 1) issue(1, 1);

    for (int ch = 0; ch < nch; ch++) {
        if (ch + 1 < nch) { CP_WAIT1(); } else { CP_WAIT0(); }
        __syncthreads();

        uint32_t* AH = smg + (ch & 1) * STAGE_U32;
        uint32_t* BH = AH + 5120;
        #pragma unroll
        for (int ks = 0; ks < 4; ks++) {
            int jc = ks * 8 + 2 * tig;
            uint32_t ahi[2][4];
            #pragma unroll
            for (int mt = 0; mt < 2; mt++) {
                int r = warp_m * 32 + mt * 16 + gid;
                uint2 h0 = *reinterpret_cast<uint2*>(&AH[r * GSTR + jc]);
                uint2 h1 = *reinterpret_cast<uint2*>(&AH[(r + 8) * GSTR + jc]);
                ahi[mt][0] = h0.x; ahi[mt][1] = h1.x; ahi[mt][2] = h0.y; ahi[mt][3] = h1.y;
            }
            uint32_t bhi[4][2];
            #pragma unroll
            for (int nt = 0; nt < 4; nt++) {
                int br = warp_n * 32 + nt * 8 + gid;
                uint2 bh = *reinterpret_cast<uint2*>(&BH[br * GSTR + jc]);
                bhi[nt][0] = bh.x; bhi[nt][1] = bh.y;
            }
            #pragma unroll
            for (int mt = 0; mt < 2; mt++)
                #pragma unroll
                for (int nt = 0; nt < 4; nt++)
                    mma_fp16(acc[mt][nt], ahi[mt], bhi[nt]);
        }
        __syncthreads();

        if (ch + 2 < nch) issue(ch + 2, ch & 1);
    }

    // ---- epilogue
    int row_base = n0 + warp_m * 32;
    int col_base = m0 + warp_n * 32;
    #pragma unroll
    for (int nt = 0; nt < 4; nt++) {
        int col = col_base + nt * 8 + 2 * tig;
        float b0 = bias[col], b1 = bias[col + 1];
        #pragma unroll
        for (int mt = 0; mt < 2; mt++) {
            #pragma unroll
            for (int half = 0; half < 2; half++) {
                int r = row_base + mt * 16 + gid + half * 8;
                float v0 = acc[mt][nt][half * 2 + 0] + b0;
                float v1 = acc[mt][nt][half * 2 + 1] + b1;
                if (EPI == 5) {
                    int idx;
                    if (col < 128) {
                        const float sc = 0.17677669529663687f;
                        v0 *= sc; v1 *= sc;
                        int p = col >> 1;
                        idx = (p & ~7) | PERMJ(p & 7);
                    } else if (col < 256) {
                        int p = (col - 128) >> 1;
                        idx = 64 + ((p & ~7) | PERMJ(p & 7));
                    } else {
                        idx = 128 + ((col - 256) >> 1);
                    }
                    outH[(long)r * 192 + idx] = f22h2(v0, v1);
                } else if (EPI == 4) {
                    v0 = 0.5f * v0 * (1.0f + erff(v0 * 0.70710678118654752f));
                    v1 = 0.5f * v1 * (1.0f + erff(v1 * 0.70710678118654752f));
                    int p = col >> 1;
                    int idx = (p & ~7) | PERMJ(p & 7);
                    outH[(long)r * 128 + idx] = f22h2(v0, v1);
                } else if (EPI == 3) {
                    float2 rv = *reinterpret_cast<const float2*>(resid + (long)r * 128 + col);
                    v0 += rv.x; v1 += rv.y;
                    long o = (long)r + (r >= 9216 ? 1170432L : 0L) + (long)col * 9216;
                    out[o]        = v0;
                    out[o + 9216] = v1;
                } else {
                    float2* dst = reinterpret_cast<float2*>(out + (long)r * M + col);
                    if (EPI == 2) {
                        float2 old = *dst;
                        v0 += old.x; v1 += old.y;
                    }
                    float2 st; st.x = v0; st.y = v1;
                    *dst = st;
                }
            }
        }
    }
}

// ===========================================================================
// fp16 tensor-core neighborhood attention (unchanged)
// ===========================================================================
#define AGSTR 24
#define VSTP  116
#define PSTP  68
#define ATTN_SMEM_U32 (224*AGSTR + 32*VSTP + 170)

__global__ void __launch_bounds__(128, 4)
attn_mma_kernel(const uint32_t* __restrict__ inH,
                const float* __restrict__ rpb,
                uint32_t* __restrict__ outH) {
    extern __shared__ uint32_t smu[];
    uint32_t* Ks = smu;
    uint32_t* Vt = Ks + 224*AGSTR;
    float*    rb = reinterpret_cast<float*>(Vt + 32*VSTP);

    int tile = blockIdx.x, head = blockIdx.y, bd = blockIdx.z;
    int h0 = (tile / 6) * 8;
    int w0 = (tile % 6) * 8;
    int kh0 = min(max(h0 - 3, 0), H_ - KW);
    int kw0 = min(max(w0 - 3, 0), W_ - KW);
    int tid = threadIdx.x;

    for (int e = tid; e < 196*4; e += 128) {
        int key = e >> 2, q = e & 3;
        int kr = key / 14, kc = key % 14;
        int gh = min(kh0 + kr, H_-1);
        int gw = min(kw0 + kc, W_-1);
        long tok = ((long)(bd*H_ + gh))*W_ + gw;
        long src = tok*192 + 64 + head*16 + q*4;
        *reinterpret_cast<uint4*>(&Ks[key*AGSTR + q*4]) = *reinterpret_cast<const uint4*>(inH + src);
    }
    for (int e = tid; e < 28*6; e += 128) {
        int key = 196 + e / 6, q = e % 6;
        *reinterpret_cast<uint4*>(&Ks[key*AGSTR + q*4]) = make_uint4(0,0,0,0);
    }
    for (int e = tid; e < 98*4; e += 128) {
        int kp = e >> 2, pq = e & 3;
        int keyA = 2*kp;
        int kr = keyA / 14, kc = keyA % 14;
        int gh = min(kh0 + kr, H_-1);
        int gwA = min(kw0 + kc, W_-1);
        int gwB = min(kw0 + kc + 1, W_-1);
        long rowb = ((long)(bd*H_ + gh))*W_;
        long sA = (rowb + gwA)*192 + 128 + head*16 + pq*4;
        long sB = (rowb + gwB)*192 + 128 + head*16 + pq*4;
        uint4 HA = *reinterpret_cast<const uint4*>(inH + sA);
        uint4 HB = *reinterpret_cast<const uint4*>(inH + sB);
        uint32_t ha[4] = {HA.x, HA.y, HA.z, HA.w};
        uint32_t hb[4] = {HB.x, HB.y, HB.z, HB.w};
        #pragma unroll
        for (int j = 0; j < 4; j++) {
            int pp = pq*4 + j;
            Vt[(2*pp+0)*VSTP + kp] = __byte_perm(ha[j], hb[j], 0x5410);
            Vt[(2*pp+1)*VSTP + kp] = __byte_perm(ha[j], hb[j], 0x7632);
        }
    }
    for (int e = tid; e < 32*14; e += 128) {
        int dm = e / 14, kp = 98 + (e % 14);
        Vt[dm*VSTP + kp] = 0;
    }
    for (int i = tid; i < 169; i += 128) rb[i] = rpb[head*169 + i];
    __syncthreads();

    int warp = tid >> 5, lane = tid & 31;
    int gid = lane >> 2, tig = lane & 3;

    int hq0 = h0 + 2*warp;
    int hq1 = hq0 + 1;
    int wq  = w0 + gid;
    long tok0 = (long)(bd*H_ + hq0)*W_ + wq;
    long tok1 = tok0 + W_;
    int rel0 = min(max(hq0-3, 0), H_-KW) - kh0;
    int rel1 = min(max(hq1-3, 0), H_-KW) - kh0;
    int ws   = min(max(wq-3, 0), W_-KW) - kw0;
    int n_base = ((min(rel0, rel1) * 14) >> 3) * 8;

    uint32_t qh[2][4];
    #pragma unroll
    for (int ks = 0; ks < 2; ks++) {
        long o0 = tok0*192 + head*16 + ks*8 + 2*tig;
        long o1 = tok1*192 + head*16 + ks*8 + 2*tig;
        uint2 h0v = *reinterpret_cast<const uint2*>(inH + o0);
        uint2 h1v = *reinterpret_cast<const uint2*>(inH + o1);
        qh[ks][0] = h0v.x; qh[ks][1] = h1v.x; qh[ks][2] = h0v.y; qh[ks][3] = h1v.y;
    }

    float acc[15][4];
    #pragma unroll
    for (int nt = 0; nt < 15; nt++)
        #pragma unroll
        for (int i = 0; i < 4; i++) acc[nt][i] = 0.f;

    #pragma unroll
    for (int nt = 0; nt < 15; nt++) {
        int key = n_base + nt*8 + gid;
        #pragma unroll
        for (int ks = 0; ks < 2; ks++) {
            int o = key*AGSTR + ks*8 + 2*tig;
            uint2 bhv = *reinterpret_cast<uint2*>(&Ks[o]);
            uint32_t bh[2] = { bhv.x, bhv.y };
            mma_fp16(acc[nt], qh[ks], bh);
        }
    }

    int bh0c = kh0 - hq0 + 6;
    int bh1c = kh0 - hq1 + 6;
    int bwc  = kw0 - wq + 6;
    float mx0 = -1e30f, mx1 = -1e30f;
    #pragma unroll
    for (int nt = 0; nt < 15; nt++) {
        #pragma unroll
        for (int cc = 0; cc < 2; cc++) {
            int n = n_base + nt*8 + 2*tig + cc;
            int kr = n / 14;
            int kc = n - kr*14;
            bool vw = (unsigned)(kc - ws) <= 6u;
            bool v0 = vw && (unsigned)(kr - rel0) <= 6u;
            bool v1 = vw && (unsigned)(kr - rel1) <= 6u;
            float s0 = v0 ? acc[nt][cc]   + rb[(bh0c+kr)*13 + bwc + kc] : -1e30f;
            float s1 = v1 ? acc[nt][2+cc] + rb[(bh1c+kr)*13 + bwc + kc] : -1e30f;
            acc[nt][cc]   = s0;
            acc[nt][2+cc] = s1;
            mx0 = fmaxf(mx0, s0);
            mx1 = fmaxf(mx1, s1);
        }
    }
    mx0 = fmaxf(mx0, __shfl_xor_sync(0xffffffffu, mx0, 1));
    mx0 = fmaxf(mx0, __shfl_xor_sync(0xffffffffu, mx0, 2));
    mx1 = fmaxf(mx1, __shfl_xor_sync(0xffffffffu, mx1, 1));
    mx1 = fmaxf(mx1, __shfl_xor_sync(0xffffffffu, mx1, 2));

    float sum0 = 0.f, sum1 = 0.f;
    #pragma unroll
    for (int nt = 0; nt < 15; nt++) {
        #pragma unroll
        for (int cc = 0; cc < 2; cc++) {
            float e0 = __expf(acc[nt][cc]   - mx0);
            float e1 = __expf(acc[nt][2+cc] - mx1);
            acc[nt][cc]   = e0;
            acc[nt][2+cc] = e1;
            sum0 += e0;
            sum1 += e1;
        }
    }
    sum0 += __shfl_xor_sync(0xffffffffu, sum0, 1);
    sum0 += __shfl_xor_sync(0xffffffffu, sum0, 2);
    sum1 += __shfl_xor_sync(0xffffffffu, sum1, 1);
    sum1 += __shfl_xor_sync(0xffffffffu, sum1, 2);
    float inv0 = 1.0f / sum0;
    float inv1 = 1.0f / sum1;

    __syncthreads();
    uint32_t* Pw = smu + warp * (16 * PSTP);
    #pragma unroll
    for (int nt = 0; nt < 15; nt++) {
        Pw[gid*PSTP + nt*4 + tig]     = f22h2(acc[nt][0], acc[nt][1]);
        Pw[(gid+8)*PSTP + nt*4 + tig] = f22h2(acc[nt][2], acc[nt][3]);
    }
    Pw[gid*PSTP + 60 + tig] = 0;
    Pw[(gid+8)*PSTP + 60 + tig] = 0;
    __syncwarp();

    int nb2 = n_base >> 1;
    float o[4][4];
    #pragma unroll
    for (int nt = 0; nt < 4; nt++)
        #pragma unroll
        for (int i = 0; i < 4; i++) o[nt][i] = 0.f;

    #pragma unroll
    for (int kt = 0; kt < 8; kt++) {
        int p0 = gid*PSTP + kt*8 + tig;
        int p1 = (gid+8)*PSTP + kt*8 + tig;
        uint32_t ph[4] = { Pw[p0], Pw[p1], Pw[p0 + 4], Pw[p1 + 4] };
        #pragma unroll
        for (int nt = 0; nt < 4; nt++) {
            int vr = (nt*8 + gid)*VSTP + nb2 + kt*8 + tig;
            uint32_t vh[2] = { Vt[vr], Vt[vr + 4] };
            mma_fp16(o[nt], ph, vh);
        }
    }

    #pragma unroll
    for (int nt = 0; nt < 4; nt++) {
        int d = head*32 + nt*8 + 2*tig;
        int p = d >> 1;
        int idx = (p & ~7) | PERMJ(p & 7);
        outH[tok0*64 + idx] = f22h2(o[nt][0]*inv0, o[nt][1]*inv0);
        outH[tok1*64 + idx] = f22h2(o[nt][2]*inv1, o[nt][3]*inv1);
    }
}

// ---------------------------------------------------------------------------
// Launch
// ---------------------------------------------------------------------------
extern "C" void kernel_launch(void* const* d_in, const int* in_sizes, int n_in,
                              void* d_out, int out_size) {
    const float* x      = (const float*)d_in[0];
    const float* n1w    = (const float*)d_in[1];
    const float* n1b    = (const float*)d_in[2];
    const float* qkv_w  = (const float*)d_in[3];
    const float* qkv_b  = (const float*)d_in[4];
    const float* rpb    = (const float*)d_in[5];
    const float* proj_w = (const float*)d_in[6];
    const float* proj_b = (const float*)d_in[7];
    const float* n2w    = (const float*)d_in[8];
    const float* n2b    = (const float*)d_in[9];
    const float* fc1_w  = (const float*)d_in[10];
    const float* fc1_b  = (const float*)d_in[11];
    const float* fc2_w  = (const float*)d_in[12];
    const float* fc2_b  = (const float*)d_in[13];
    float* out = (float*)d_out;

    float *t_p;
    uint32_t *wh_p, *ah_p, *bh_p, *qh_p;
    cudaGetSymbolAddress((void**)&t_p,  g_t);
    cudaGetSymbolAddress((void**)&wh_p, g_wh);
    cudaGetSymbolAddress((void**)&ah_p, g_ah);
    cudaGetSymbolAddress((void**)&bh_p, g_bh);
    cudaGetSymbolAddress((void**)&qh_p, g_qkvh);

    int attn_smem = ATTN_SMEM_U32 * (int)sizeof(uint32_t);
    cudaFuncSetAttribute(attn_mma_kernel, cudaFuncAttributeMaxDynamicSharedMemorySize, attn_smem);
    cudaFuncSetAttribute(gemm_cp_kernel<2>, cudaFuncAttributeMaxDynamicSharedMemorySize, GEMM_SMEM);
    cudaFuncSetAttribute(gemm_cp_kernel<3>, cudaFuncAttributeMaxDynamicSharedMemorySize, GEMM_SMEM);
    cudaFuncSetAttribute(gemm_cp_kernel<4>, cudaFuncAttributeMaxDynamicSharedMemorySize, GEMM_SMEM);
    cudaFuncSetAttribute(gemm_cp_kernel<5>, cudaFuncAttributeMaxDynamicSharedMemorySize, GEMM_SMEM);

    // 0. convert weights to fp16 pairs
    wsplit_kernel<<<256, 256>>>(qkv_w, proj_w, fc1_w, fc2_w);
    // 1+2. fused transpose-in + LN1 + fp16 convert
    t_ln_kernel<<<B_*D_*H_, 256>>>(x, n1w, n1b, t_p, ah_p);
    // 3. qkv GEMM -> fp16 Q(scaled)/K/V   (M=384, K=128)
    gemm_cp_kernel<5><<<dim3(6, NTOK/128), 256, GEMM_SMEM>>>(
        ah_p, wh_p, qkv_b, nullptr, qh_p, nullptr, 384, 128);
    // 4. neighborhood attention -> fp16 out
    attn_mma_kernel<<<dim3(36, NHEAD, B_*D_), 128, attn_smem>>>(qh_p, rpb, ah_p);
    // 5. t += attn @ proj_w^T + b     (M=128, K=128)
    gemm_cp_kernel<2><<<dim3(2, NTOK/128), 256, GEMM_SMEM>>>(
        ah_p, wh_p + 24576, proj_b, t_p, nullptr, nullptr, 128, 128);
    // 6. LN2 + fp16 convert
    ln_prep_kernel<<<NTOK/8, 256>>>(t_p, n2w, n2b, ah_p);
    // 7. h1 = gelu(LN2(t) @ fc1_w^T + b) -> fp16  (M=256, K=128)
    gemm_cp_kernel<4><<<dim3(4, NTOK/128), 256, GEMM_SMEM>>>(
        ah_p, wh_p + 32768, fc1_b, nullptr, bh_p, nullptr, 256, 128);
    // 8. out = transpose(t + h1 @ fc2_w^T + b)   (M=128, K=256)
    gemm_cp_kernel<3><<<dim3(2, NTOK/128), 256, GEMM_SMEM>>>(
        bh_p, wh_p + 49152, fc2_b, out, nullptr, t_p, 128, 256);
}